// round 15
// baseline (speedup 1.0000x reference)
#include <cuda_runtime.h>
#include <cuda_bf16.h>
#include <cstdint>

#define CIN   256
#define EDIM  16
#define LWIN  64
#define MDIM  64
#define HDIM  64
#define COUT  256
#define BATCH 16
#define NSTEP 2048

// ---------------- scratch ----------------
__device__ float g_TW[CIN * LWIN * HDIM];
__device__ float g_Tb[CIN * LWIN * HDIM];
__device__ float g_preW[NSTEP * BATCH * HDIM];
__device__ float g_preb[NSTEP * BATCH * HDIM];
__device__ float g_m[NSTEP * BATCH * MDIM];

__device__ __forceinline__ float sigmoidf_fast(float x) {
    return 1.0f / (1.0f + __expf(-x));
}
__device__ __forceinline__ unsigned long long packf2(float lo, float hi) {
    unsigned long long r;
    asm("mov.b64 %0, {%1, %2};" : "=l"(r) : "f"(lo), "f"(hi));
    return r;
}
__device__ __forceinline__ unsigned long long fma2(unsigned long long a,
                                                   unsigned long long b,
                                                   unsigned long long c) {
    unsigned long long d;
    asm("fma.rn.f32x2 %0, %1, %2, %3;" : "=l"(d) : "l"(a), "l"(b), "l"(c));
    return d;
}
__device__ __forceinline__ unsigned long long add2(unsigned long long a,
                                                   unsigned long long b) {
    unsigned long long d;
    asm("add.rn.f32x2 %0, %1, %2;" : "=l"(d) : "l"(a), "l"(b));
    return d;
}
__device__ __forceinline__ float hsum2(unsigned long long v) {
    float lo, hi;
    asm("mov.b64 {%0, %1}, %2;" : "=f"(lo), "=f"(hi) : "l"(v));
    return lo + hi;
}

// ---------------- kernel 1: token/position contribution tables ----------------
__global__ void table_kernel(const float* __restrict__ emb,
                             const float* __restrict__ Wew,
                             const float* __restrict__ bew) {
    int c = blockIdx.x >> 6;
    int l = blockIdx.x & 63;
    int h = threadIdx.x;
    float aw = 0.f, ab = 0.f;
#pragma unroll
    for (int e = 0; e < EDIM; ++e) {
        float ev = emb[c * EDIM + e];
        int row = MDIM + l * EDIM + e;
        aw += ev * Wew[row * HDIM + h];
        ab += ev * bew[row * HDIM + h];
    }
    g_TW[(c * LWIN + l) * HDIM + h] = aw;
    g_Tb[(c * LWIN + l) * HDIM + h] = ab;
}

// ---------------- kernel 2: window pre-activations ----------------
__global__ void pre_kernel(const int* __restrict__ x0) {
    int tb = blockIdx.x;
    int t = tb >> 4, b = tb & 15;
    int h = threadIdx.x;
    float aw = 0.f, ab = 0.f;
#pragma unroll 4
    for (int l = 0; l < LWIN; ++l) {
        int k = t + l;
        int tok = (k < LWIN) ? 0 : x0[b * NSTEP + (k - LWIN)];
        aw += g_TW[(tok * LWIN + l) * HDIM + h];
        ab += g_Tb[(tok * LWIN + l) * HDIM + h];
    }
    g_preW[(t * BATCH + b) * HDIM + h] = aw;
    g_preb[(t * BATCH + b) * HDIM + h] = ab;
}

// ---------------- kernel 3: scan + fused loss ----------------
// 16 clusters (batch) x 8 CTAs (i-slices of 8), 512 threads/CTA.
// Cross-CTA per-step sync: payload (2x u64 DSMEM stores) + step-number flag
// (st.release.cluster). Consumers spin on LOCAL smem flags. No barrier.cluster
// inside the loop. Loss epilogue fused after one final cluster sync.
__global__ void __launch_bounds__(512, 1)
scan_kernel(const float* __restrict__ Wew, const float* __restrict__ Web,
            const float* __restrict__ Wdw, const float* __restrict__ Wdb,
            const float* __restrict__ bew, const float* __restrict__ beb,
            const float* __restrict__ bdw, const float* __restrict__ bdb,
            const int* __restrict__ x0, const float* __restrict__ decw,
            const float* __restrict__ decb, float* __restrict__ out) {
    extern __shared__ float sDecw[];              // 64 KB dynamic (loss phase)
    __shared__ __align__(16) float sM[2][MDIM];   // ping-pong m
    __shared__ __align__(16) float sH[2][HDIM];   // hW, hb
    __shared__ __align__(16) float sG[512];       // G[il][h]
    __shared__ __align__(16) float sBdw[512];     // bdw[h, ig] -> [il][h]
    __shared__ __align__(16) float sWdb[512];     // Wdb[ig*64+j] -> [il][j]
    __shared__ __align__(16) float sP[512];       // enc partials
    __shared__ __align__(16) float sRows[16 * 64];// loss staging
    __shared__ unsigned sFlag[2][2][8];           // [half][buf][src] step flags

    const int tid = threadIdx.x;
    const int b = blockIdx.x >> 3;
    const int r = blockIdx.x & 7;

    // ---- G identity: gil = tid>>6 (0..7), gh = tid&63
    const int gil = tid >> 6, gh = tid & 63;
    const int ig_g = r * 8 + gil;
    unsigned long long wgp[32];
    {
        const float* wsrc = Wdw + gh * 4096 + ig_g * 64;
#pragma unroll
        for (int k = 0; k < 32; ++k)
            wgp[k] = packf2(wsrc[2 * k], wsrc[2 * k + 1]);
    }

    // ---- enc identity: q = tid>>7, path, h6 (4-way split over j)
    const int q = tid >> 7;
    const int rest = tid & 127;
    const int path = rest >> 6;
    const int h6 = rest & 63;
    const float* Aarr = path ? bew : Wew;
    unsigned long long aencp[8];
#pragma unroll
    for (int k = 0; k < 8; ++k)
        aencp[k] = packf2(Aarr[(q * 16 + 2 * k) * 64 + h6],
                          Aarr[(q * 16 + 2 * k + 1) * 64 + h6]);

    // ---- stage B identity (tid<64): thread handles (pathW,h=tid) and (pathb,h=tid)
    float encbW = 0.f, encbB = 0.f;
    const float* ppW = nullptr;
    const float* ppB = nullptr;
    float preW_next = 0.f, preB_next = 0.f;
    float bdbv = 0.f;
    if (tid < 64) {
        encbW = Web[tid];
        encbB = beb[tid];
        ppW = g_preW + b * 64 + tid;
        ppB = g_preb + b * 64 + tid;
        preW_next = ppW[0];
        preB_next = ppB[0];
        bdbv = bdb[r * 8 + (tid >> 3)];
    }

    // small weight tables in smem
    {
        int il = tid >> 6, hh = tid & 63;
        sBdw[il * 64 + hh] = bdw[hh * 64 + r * 8 + il];
        sWdb[il * 64 + hh] = Wdb[(r * 8 + il) * 64 + hh];
    }
    if (tid < 64) sM[0][tid] = 0.f;
    if (tid < 32) ((unsigned*)sFlag)[tid] = 0u;

    const uint32_t sM_sa = (uint32_t)__cvta_generic_to_shared(&sM[0][0]);
    const uint32_t sF_sa = (uint32_t)__cvta_generic_to_shared(&sFlag[0][0][0]);

    __syncthreads();
    // one-time cluster sync: all CTAs initialized before any remote store
    asm volatile("barrier.cluster.arrive.aligned;\n" ::: "memory");
    asm volatile("barrier.cluster.wait.aligned;\n" ::: "memory");

#pragma unroll 1
    for (int t = 0; t < NSTEP; ++t) {
        // ---- poll: local smem flags for buf t&1 reach value >= t
        if (t > 0 && tid < 16) {
            int src = tid & 7, half = tid >> 3;
            if (src != r) {
                uint32_t fa = sF_sa + (((half << 1) + (t & 1)) * 8 + src) * 4;
                unsigned v;
                do {
                    asm volatile("ld.acquire.cluster.shared::cta.u32 %0, [%1];"
                                 : "=r"(v) : "r"(fa) : "memory");
                } while (v < (unsigned)t);
            }
        }
        __syncthreads();

        const uint32_t mcur_sa = sM_sa + (t & 1) * (MDIM * 4);

        // ---- stage A: G (all 512) and enc partials (all 512), parallel
        {
            unsigned long long g0 = 0ull, g1 = 0ull;
#pragma unroll
            for (int k = 0; k < 16; ++k) {
                unsigned long long m0, m1;
                asm volatile("ld.shared.v2.u64 {%0, %1}, [%2];"
                             : "=l"(m0), "=l"(m1) : "r"(mcur_sa + k * 16));
                g0 = fma2(m0, wgp[2 * k], g0);
                g1 = fma2(m1, wgp[2 * k + 1], g1);
            }
            sG[gil * 64 + gh] = hsum2(add2(g0, g1));

            unsigned long long e0 = 0ull, e1 = 0ull;
            uint32_t ma = mcur_sa + q * 64;
#pragma unroll
            for (int k = 0; k < 4; ++k) {
                unsigned long long m0, m1;
                asm volatile("ld.shared.v2.u64 {%0, %1}, [%2];"
                             : "=l"(m0), "=l"(m1) : "r"(ma + k * 16));
                e0 = fma2(m0, aencp[2 * k], e0);
                e1 = fma2(m1, aencp[2 * k + 1], e1);
            }
            sP[q * 128 + rest] = hsum2(add2(e0, e1));
        }
        __syncthreads();

        // ---- stages B + C on warps 0-1 only
        if (tid < 64) {
            // B: finalize both paths for h=tid
            float zW = sP[tid] + sP[128 + tid] + sP[256 + tid] + sP[384 + tid]
                     + preW_next + encbW;
            float zB = sP[64 + tid] + sP[192 + tid] + sP[320 + tid] + sP[448 + tid]
                     + preB_next + encbB;
            sH[0][tid] = sigmoidf_fast(zW);
            sH[1][tid] = sigmoidf_fast(zB);
            if (t + 1 < NSTEP) {
                preW_next = ppW[(t + 1) * (BATCH * 64)];
                preB_next = ppB[(t + 1) * (BATCH * 64)];
            }
            asm volatile("bar.sync 1, 64;" ::: "memory");

            // C: res[i] via h-contraction + bias paths
            const int il = tid >> 3, s8 = tid & 7;
            const int base = il * 64 + s8 * 8;
            const float* mcur = sM[t & 1];
            float acc = 0.f;
#pragma unroll
            for (int k = 0; k < 8; ++k) {
                int hh = s8 * 8 + k;
                acc += sH[0][hh] * sG[base + k];
                acc += sH[1][hh] * sBdw[base + k];
                acc += mcur[hh] * sWdb[base + k];
            }
            acc += __shfl_xor_sync(0xffffffffu, acc, 1);
            acc += __shfl_xor_sync(0xffffffffu, acc, 2);
            acc += __shfl_xor_sync(0xffffffffu, acc, 4);
            // every lane now has its group's total
            float nm = sigmoidf_fast(acc + bdbv);
            const int nxt = (t + 1) & 1;
            if (s8 == 0) {
                int igo = r * 8 + il;
                sM[nxt][igo] = nm;                       // local copy
                g_m[(t * BATCH + b) * MDIM + igo] = nm;  // persist for loss
            }
            // gather this warp's 4 group-values (warp0: il0-3, warp1: il4-7)
            float v0 = __shfl_sync(0xffffffffu, nm, 0);
            float v1 = __shfl_sync(0xffffffffu, nm, 8);
            float v2 = __shfl_sync(0xffffffffu, nm, 16);
            float v3 = __shfl_sync(0xffffffffu, nm, 24);
            const int lane = tid & 31;
            const int half = tid >> 5;                   // 0: il0-3, 1: il4-7
            if (t + 1 < NSTEP && lane < 8 && lane != r) {
                unsigned long long d0 = packf2(v0, v1);
                unsigned long long d1 = packf2(v2, v3);
                uint32_t dst = sM_sa + nxt * (MDIM * 4) + r * 32 + half * 16;
                uint32_t fad = sF_sa + (((half << 1) + nxt) * 8 + r) * 4;
                uint32_t ra, rf;
                asm volatile("mapa.shared::cluster.u32 %0, %1, %2;"
                             : "=r"(ra) : "r"(dst), "r"(lane));
                asm volatile("mapa.shared::cluster.u32 %0, %1, %2;"
                             : "=r"(rf) : "r"(fad), "r"(lane));
                asm volatile("st.shared::cluster.u64 [%0], %1;" :: "r"(ra), "l"(d0) : "memory");
                asm volatile("st.shared::cluster.u64 [%0], %1;" :: "r"(ra + 8), "l"(d1) : "memory");
                asm volatile("st.release.cluster.shared::cluster.u32 [%0], %1;"
                             :: "r"(rf), "r"((unsigned)(t + 1)) : "memory");
            }
        }
        // warps 2-15 loop straight to the top __syncthreads
    }

    // ---- final cluster sync: all g_m stores visible cluster-wide
    asm volatile("barrier.cluster.arrive.aligned;\n" ::: "memory");
    asm volatile("barrier.cluster.wait.aligned;\n" ::: "memory");

    // ================= fused loss epilogue =================
    // this CTA handles t in [r*256, (r+1)*256) for batch b
    for (int idx = tid; idx < 64 * 256; idx += 512)
        sDecw[idx] = decw[idx];
    const int lane = tid & 31, w = tid >> 5;
    float db[8];
#pragma unroll
    for (int k = 0; k < 8; ++k)
        db[k] = decb[lane * 8 + k];
    __syncthreads();

#pragma unroll 1
    for (int iter = 0; iter < 16; ++iter) {
        const int tbase = r * 256 + iter * 16;
        // stage 16 m-rows into smem
        {
            int rw = tid >> 5, cp = (tid & 31) * 2;
            const float2 src = *(const float2*)(g_m + ((tbase + rw) * BATCH + b) * 64 + cp);
            *(float2*)(sRows + rw * 64 + cp) = src;
        }
        __syncthreads();

        const int t = tbase + w;
        float lc[8];
#pragma unroll
        for (int k = 0; k < 8; ++k) lc[k] = db[k];
        const float* mrow = sRows + w * 64;
#pragma unroll 8
        for (int i = 0; i < 64; ++i) {
            float mi = mrow[i];
            const float4 w0 = *(const float4*)(sDecw + i * 256 + lane * 8);
            const float4 w1 = *(const float4*)(sDecw + i * 256 + lane * 8 + 4);
            lc[0] += mi * w0.x; lc[1] += mi * w0.y; lc[2] += mi * w0.z; lc[3] += mi * w0.w;
            lc[4] += mi * w1.x; lc[5] += mi * w1.y; lc[6] += mi * w1.z; lc[7] += mi * w1.w;
        }
        int y = x0[b * NSTEP + t];
        float mx = lc[0];
#pragma unroll
        for (int k = 1; k < 8; ++k) mx = fmaxf(mx, lc[k]);
#pragma unroll
        for (int off = 16; off; off >>= 1)
            mx = fmaxf(mx, __shfl_xor_sync(0xffffffffu, mx, off));
        float S = 0.f;
#pragma unroll
        for (int k = 0; k < 8; ++k) S += __expf(lc[k] - mx);
#pragma unroll
        for (int off = 16; off; off >>= 1)
            S += __shfl_xor_sync(0xffffffffu, S, off);
        float lyl = 0.f;
        const int yk = y & 7;
#pragma unroll
        for (int k = 0; k < 8; ++k) lyl = (k == yk) ? lc[k] : lyl;
        float ly = __shfl_sync(0xffffffffu, lyl, y >> 3);
        if (lane == 0)
            out[t * BATCH + b] = (mx + __logf(S) - ly) * 1.4426950408889634f;
        __syncthreads();
    }
}

// ---------------- launch ----------------
extern "C" void kernel_launch(void* const* d_in, const int* in_sizes, int n_in,
                              void* d_out, int out_size) {
    const int*   x0   = (const int*)d_in[0];
    const float* emb  = (const float*)d_in[1];
    const float* Wew  = (const float*)d_in[2];
    const float* Web  = (const float*)d_in[3];
    const float* Wdw  = (const float*)d_in[4];
    const float* Wdb  = (const float*)d_in[5];
    const float* bew  = (const float*)d_in[6];
    const float* beb  = (const float*)d_in[7];
    const float* bdw  = (const float*)d_in[8];
    const float* bdb  = (const float*)d_in[9];
    const float* decw = (const float*)d_in[10];
    const float* decb = (const float*)d_in[11];
    float* out = (float*)d_out;

    table_kernel<<<CIN * LWIN, 64>>>(emb, Wew, bew);
    pre_kernel<<<NSTEP * BATCH, 64>>>(x0);

    static int smem_set = 0;
    if (!smem_set) {
        cudaFuncSetAttribute(scan_kernel,
                             cudaFuncAttributeMaxDynamicSharedMemorySize, 65536);
        smem_set = 1;
    }

    cudaLaunchConfig_t cfg = {};
    cfg.gridDim = dim3(128, 1, 1);
    cfg.blockDim = dim3(512, 1, 1);
    cfg.dynamicSmemBytes = 65536;
    cfg.stream = 0;
    cudaLaunchAttribute attr[1];
    attr[0].id = cudaLaunchAttributeClusterDimension;
    attr[0].val.clusterDim.x = 8;
    attr[0].val.clusterDim.y = 1;
    attr[0].val.clusterDim.z = 1;
    cfg.attrs = attr;
    cfg.numAttrs = 1;
    cudaLaunchKernelEx(&cfg, scan_kernel, Wew, Web, Wdw, Wdb, bew, beb, bdw, bdb,
                       x0, decw, decb, out);
}